// round 14
// baseline (speedup 1.0000x reference)
#include <cuda_runtime.h>
#include <cuda_bf16.h>
#include <cstdint>

#define BB    1024
#define INF   4096
#define OUTF  4096
#define KF    64
#define TOPK  64
#define MAXC  80      // approx candidates kept for exact rescore
#define SORTN 128     // padded bitonic size

// 32MB bf16 transposed-weight scratch: g_wtb[i*OUTF + o] = bf16(W[o*INF + i])
__device__ __nv_bfloat16 g_wtb[(size_t)INF * OUTF];

// ---------------------------------------------------------------------------
// Kernel 1: tiled transpose + fp32->bf16 convert. 64x64 tile, 256 threads.
// ---------------------------------------------------------------------------
__global__ __launch_bounds__(256) void transpose_kernel(const float* __restrict__ W) {
    __shared__ float tile[64][65];
    const int t  = threadIdx.x;
    const int tx = t & 15;
    const int ty = t >> 4;
    const int ibase = blockIdx.x * 64;
    const int obase = blockIdx.y * 64;

    const float4* W4 = (const float4*)W;
#pragma unroll
    for (int rr = 0; rr < 4; rr++) {
        int ol = ty + rr * 16;
        float4 v = __ldcs(&W4[(size_t)(obase + ol) * (INF / 4) + (ibase >> 2) + tx]);
        tile[4 * tx + 0][ol] = v.x;
        tile[4 * tx + 1][ol] = v.y;
        tile[4 * tx + 2][ol] = v.z;
        tile[4 * tx + 3][ol] = v.w;
    }
    __syncthreads();

    const int oc = t & 15;
    const int iy = t >> 4;
#pragma unroll
    for (int rr = 0; rr < 4; rr++) {
        int il = iy + rr * 16;
        __nv_bfloat162 p0 = __floats2bfloat162_rn(tile[il][4 * oc + 0], tile[il][4 * oc + 1]);
        __nv_bfloat162 p1 = __floats2bfloat162_rn(tile[il][4 * oc + 2], tile[il][4 * oc + 3]);
        uint2 pk;
        pk.x = *reinterpret_cast<unsigned*>(&p0);
        pk.y = *reinterpret_cast<unsigned*>(&p1);
        *reinterpret_cast<uint2*>(&g_wtb[(size_t)(ibase + il) * OUTF + obase + 4 * oc]) = pk;
    }
}

// ---------------------------------------------------------------------------
// float <-> order-preserving uint32 key
// ---------------------------------------------------------------------------
__device__ __forceinline__ unsigned f2key(float f) {
    unsigned u = __float_as_uint(f);
    return u ^ ((u & 0x80000000u) ? 0xFFFFFFFFu : 0x80000000u);
}
__device__ __forceinline__ float key2f(unsigned k) {
    unsigned u = k ^ ((k & 0x80000000u) ? 0x80000000u : 0xFFFFFFFFu);
    return __uint_as_float(u);
}

// ---------------------------------------------------------------------------
// Kernel 2: one block per batch row.
//   1) approx scores from bf16 scratch (8 consecutive o per thread, LDG.128/k)
//   2) radix-select the MAXC-th largest approx composite, collect MAXC cands
//   3) exact fp32 rescore of candidates from original W (4-thread groups)
//   4) bitonic sort 128 (padded) exact composites desc, write top 64
// ---------------------------------------------------------------------------
__global__ __launch_bounds__(512) void router_kernel(
    const float* __restrict__ x, const float* __restrict__ W,
    const float* __restrict__ bias, const int* __restrict__ pidx,
    float* __restrict__ out, int write_idx)
{
    __shared__ float sx[KF];
    __shared__ int   sc[KF];
    __shared__ unsigned hist[256];
    __shared__ unsigned long long s_prefix;
    __shared__ int s_target;
    __shared__ unsigned long long s_top[SORTN];
    __shared__ int s_cnt;

    const int b = blockIdx.x;
    const int tid = threadIdx.x;

    if (tid < KF) { sx[tid] = x[b * KF + tid]; sc[tid] = pidx[b * KF + tid]; }
    if (tid == 0) { s_prefix = 0ULL; s_target = MAXC; s_cnt = 0; }
    __syncthreads();

    // ---- approx gather matvec: 8 consecutive o per thread ------------------
    const int o0 = tid * 8;
    float acc[8];
    {
        const float4* b4 = (const float4*)(bias + o0);
        float4 bb0 = b4[0], bb1 = b4[1];
        acc[0] = bb0.x; acc[1] = bb0.y; acc[2] = bb0.z; acc[3] = bb0.w;
        acc[4] = bb1.x; acc[5] = bb1.y; acc[6] = bb1.z; acc[7] = bb1.w;
    }
#pragma unroll 8
    for (int k = 0; k < KF; k++) {
        float xv = sx[k];
        uint4 wv = *reinterpret_cast<const uint4*>(&g_wtb[(size_t)sc[k] * OUTF + o0]);
        __nv_bfloat162 h0 = *reinterpret_cast<__nv_bfloat162*>(&wv.x);
        __nv_bfloat162 h1 = *reinterpret_cast<__nv_bfloat162*>(&wv.y);
        __nv_bfloat162 h2 = *reinterpret_cast<__nv_bfloat162*>(&wv.z);
        __nv_bfloat162 h3 = *reinterpret_cast<__nv_bfloat162*>(&wv.w);
        float2 f0 = __bfloat1622float2(h0);
        float2 f1 = __bfloat1622float2(h1);
        float2 f2 = __bfloat1622float2(h2);
        float2 f3 = __bfloat1622float2(h3);
        acc[0] += xv * f0.x; acc[1] += xv * f0.y;
        acc[2] += xv * f1.x; acc[3] += xv * f1.y;
        acc[4] += xv * f2.x; acc[5] += xv * f2.y;
        acc[6] += xv * f3.x; acc[7] += xv * f3.y;
    }

    // ---- approx composites --------------------------------------------------
    unsigned long long comp[8];
#pragma unroll
    for (int j = 0; j < 8; j++)
        comp[j] = ((unsigned long long)f2key(acc[j]) << 32) |
                  (unsigned)(OUTF - 1 - (o0 + j));

    // ---- radix select: exact MAXC-th largest approx composite ---------------
    for (int p = 7; p >= 0; p--) {
        if (tid < 256) hist[tid] = 0;
        __syncthreads();
        const unsigned long long prefix_cur = s_prefix;
        const unsigned long long hi_mask = (p == 7) ? 0ULL : (~0ULL << ((p + 1) * 8));
#pragma unroll
        for (int j = 0; j < 8; j++) {
            if ((comp[j] & hi_mask) == prefix_cur)
                atomicAdd(&hist[(unsigned)(comp[j] >> (p * 8)) & 255u], 1u);
        }
        __syncthreads();
        for (int off = 1; off < 256; off <<= 1) {
            unsigned vv = 0;
            if (tid < 256 && tid + off < 256) vv = hist[tid + off];
            __syncthreads();
            if (tid < 256) hist[tid] += vv;
            __syncthreads();
        }
        int tgt = s_target;
        __syncthreads();
        if (tid < 256) {
            unsigned sv = hist[tid];
            unsigned sn = (tid < 255) ? hist[tid + 1] : 0u;
            if ((int)sv >= tgt && (int)sn < tgt) {
                s_prefix = prefix_cur | ((unsigned long long)tid << (p * 8));
                s_target = tgt - (int)sn;
            }
        }
        __syncthreads();
    }
    const unsigned long long T = s_prefix;   // exact MAXC-th largest approx

    // ---- collect the MAXC candidates ---------------------------------------
#pragma unroll
    for (int j = 0; j < 8; j++) {
        if (comp[j] >= T) {
            int pos = atomicAdd(&s_cnt, 1);
            if (pos < SORTN) s_top[pos] = comp[j];
        }
    }
    __syncthreads();

    // ---- exact rescore: 4-thread groups, one candidate each ----------------
    {
        const int c = tid >> 2;          // 0..127
        const int l4 = tid & 3;
        if (c < MAXC) {
            int oc = OUTF - 1 - (int)(s_top[c] & 0xFFFFFFFFu);
            const float* wrow = W + (size_t)oc * INF;
            float part = 0.f;
#pragma unroll 4
            for (int k = l4; k < KF; k += 4)
                part += sx[k] * __ldg(&wrow[sc[k]]);
            part += __shfl_down_sync(0xFFFFFFFFu, part, 2);
            part += __shfl_down_sync(0xFFFFFFFFu, part, 1);
            if (l4 == 0) {
                float ex = part + bias[oc];
                s_top[c] = ((unsigned long long)f2key(ex) << 32) |
                           (unsigned)(OUTF - 1 - oc);
            }
        } else if (l4 == 0) {
            s_top[c] = 0ULL;             // pad: smallest possible composite
        }
    }
    __syncthreads();

    // ---- bitonic sort descending (SORTN=128 elements) -----------------------
    for (int k2 = 2; k2 <= SORTN; k2 <<= 1) {
        for (int j = k2 >> 1; j > 0; j >>= 1) {
            if (tid < SORTN) {
                int ixj = tid ^ j;
                if (ixj > tid) {
                    bool desc = ((tid & k2) == 0);
                    unsigned long long aa = s_top[tid], bb2 = s_top[ixj];
                    if (desc ? (aa < bb2) : (aa > bb2)) {
                        s_top[tid] = bb2; s_top[ixj] = aa;
                    }
                }
            }
            __syncthreads();
        }
    }

    // ---- write: [B*64 vals][B*64 indices-as-float] -------------------------
    if (tid < TOPK) {
        unsigned long long c = s_top[tid];
        out[b * TOPK + tid] = key2f((unsigned)(c >> 32));
        if (write_idx)
            out[BB * TOPK + b * TOPK + tid] =
                (float)(OUTF - 1 - (int)(c & 0xFFFFFFFFu));
    }
}

// ---------------------------------------------------------------------------
extern "C" void kernel_launch(void* const* d_in, const int* in_sizes, int n_in,
                              void* d_out, int out_size) {
    const float* x    = (const float*)d_in[0];
    const float* w    = (const float*)d_in[1];
    const float* bias = (const float*)d_in[2];
    const int*   pidx = (const int*)d_in[3];
    (void)n_in;

    dim3 tg(INF / 64, OUTF / 64);
    transpose_kernel<<<tg, 256>>>(w);

    int write_idx = (out_size >= 2 * BB * TOPK) ? 1 : 0;
    router_kernel<<<BB, 512>>>(x, w, bias, pidx, (float*)d_out, write_idx);
}

// round 15
// speedup vs baseline: 1.0025x; 1.0025x over previous
#include <cuda_runtime.h>
#include <cuda_bf16.h>
#include <cstdint>

#define BB    1024
#define INF   4096
#define OUTF  4096
#define KF    64
#define TOPK  64
#define MAXC  80      // approx candidates kept for exact rescore
#define SORTN 128     // padded bitonic size

// 32MB bf16 transposed-weight scratch: g_wtb[i*OUTF + o] = bf16(W[o*INF + i])
__device__ __nv_bfloat16 g_wtb[(size_t)INF * OUTF];

// ---------------------------------------------------------------------------
// Kernel 1: tiled transpose + fp32->bf16 convert. 64x64 tile, 256 threads.
// W read with NORMAL caching: W (64MB) must stay L2-resident for the exact
// rescore in kernel 2 (the __ldcs evict-first hint in R14 forced those
// rescore reads to DRAM and cost ~30us of latency-exposed tail).
// ---------------------------------------------------------------------------
__global__ __launch_bounds__(256) void transpose_kernel(const float* __restrict__ W) {
    __shared__ float tile[64][65];
    const int t  = threadIdx.x;
    const int tx = t & 15;
    const int ty = t >> 4;
    const int ibase = blockIdx.x * 64;
    const int obase = blockIdx.y * 64;

    const float4* W4 = (const float4*)W;
#pragma unroll
    for (int rr = 0; rr < 4; rr++) {
        int ol = ty + rr * 16;
        float4 v = __ldg(&W4[(size_t)(obase + ol) * (INF / 4) + (ibase >> 2) + tx]);
        tile[4 * tx + 0][ol] = v.x;
        tile[4 * tx + 1][ol] = v.y;
        tile[4 * tx + 2][ol] = v.z;
        tile[4 * tx + 3][ol] = v.w;
    }
    __syncthreads();

    const int oc = t & 15;
    const int iy = t >> 4;
#pragma unroll
    for (int rr = 0; rr < 4; rr++) {
        int il = iy + rr * 16;
        __nv_bfloat162 p0 = __floats2bfloat162_rn(tile[il][4 * oc + 0], tile[il][4 * oc + 1]);
        __nv_bfloat162 p1 = __floats2bfloat162_rn(tile[il][4 * oc + 2], tile[il][4 * oc + 3]);
        uint2 pk;
        pk.x = *reinterpret_cast<unsigned*>(&p0);
        pk.y = *reinterpret_cast<unsigned*>(&p1);
        *reinterpret_cast<uint2*>(&g_wtb[(size_t)(ibase + il) * OUTF + obase + 4 * oc]) = pk;
    }
}

// ---------------------------------------------------------------------------
// float <-> order-preserving uint32 key
// ---------------------------------------------------------------------------
__device__ __forceinline__ unsigned f2key(float f) {
    unsigned u = __float_as_uint(f);
    return u ^ ((u & 0x80000000u) ? 0xFFFFFFFFu : 0x80000000u);
}
__device__ __forceinline__ float key2f(unsigned k) {
    unsigned u = k ^ ((k & 0x80000000u) ? 0x80000000u : 0xFFFFFFFFu);
    return __uint_as_float(u);
}

// ---------------------------------------------------------------------------
// Kernel 2: one block per batch row.
//   1) approx scores from bf16 scratch (8 consecutive o per thread, LDG.128/k)
//   2) radix-select the MAXC-th largest approx composite, collect MAXC cands
//   3) exact fp32 rescore of candidates from original W (4-thread groups,
//      L2-hit now that W is resident)
//   4) bitonic sort 128 (padded) exact composites desc, write top 64
// ---------------------------------------------------------------------------
__global__ __launch_bounds__(512) void router_kernel(
    const float* __restrict__ x, const float* __restrict__ W,
    const float* __restrict__ bias, const int* __restrict__ pidx,
    float* __restrict__ out, int write_idx)
{
    __shared__ float sx[KF];
    __shared__ int   sc[KF];
    __shared__ unsigned hist[256];
    __shared__ unsigned long long s_prefix;
    __shared__ int s_target;
    __shared__ unsigned long long s_top[SORTN];
    __shared__ int s_cnt;

    const int b = blockIdx.x;
    const int tid = threadIdx.x;

    if (tid < KF) { sx[tid] = x[b * KF + tid]; sc[tid] = pidx[b * KF + tid]; }
    if (tid == 0) { s_prefix = 0ULL; s_target = MAXC; s_cnt = 0; }
    __syncthreads();

    // ---- approx gather matvec: 8 consecutive o per thread ------------------
    const int o0 = tid * 8;
    float acc[8];
    {
        const float4* b4 = (const float4*)(bias + o0);
        float4 bb0 = b4[0], bb1 = b4[1];
        acc[0] = bb0.x; acc[1] = bb0.y; acc[2] = bb0.z; acc[3] = bb0.w;
        acc[4] = bb1.x; acc[5] = bb1.y; acc[6] = bb1.z; acc[7] = bb1.w;
    }
#pragma unroll 8
    for (int k = 0; k < KF; k++) {
        float xv = sx[k];
        uint4 wv = *reinterpret_cast<const uint4*>(&g_wtb[(size_t)sc[k] * OUTF + o0]);
        __nv_bfloat162 h0 = *reinterpret_cast<__nv_bfloat162*>(&wv.x);
        __nv_bfloat162 h1 = *reinterpret_cast<__nv_bfloat162*>(&wv.y);
        __nv_bfloat162 h2 = *reinterpret_cast<__nv_bfloat162*>(&wv.z);
        __nv_bfloat162 h3 = *reinterpret_cast<__nv_bfloat162*>(&wv.w);
        float2 f0 = __bfloat1622float2(h0);
        float2 f1 = __bfloat1622float2(h1);
        float2 f2 = __bfloat1622float2(h2);
        float2 f3 = __bfloat1622float2(h3);
        acc[0] += xv * f0.x; acc[1] += xv * f0.y;
        acc[2] += xv * f1.x; acc[3] += xv * f1.y;
        acc[4] += xv * f2.x; acc[5] += xv * f2.y;
        acc[6] += xv * f3.x; acc[7] += xv * f3.y;
    }

    // ---- approx composites --------------------------------------------------
    unsigned long long comp[8];
#pragma unroll
    for (int j = 0; j < 8; j++)
        comp[j] = ((unsigned long long)f2key(acc[j]) << 32) |
                  (unsigned)(OUTF - 1 - (o0 + j));

    // ---- radix select: exact MAXC-th largest approx composite ---------------
    for (int p = 7; p >= 0; p--) {
        if (tid < 256) hist[tid] = 0;
        __syncthreads();
        const unsigned long long prefix_cur = s_prefix;
        const unsigned long long hi_mask = (p == 7) ? 0ULL : (~0ULL << ((p + 1) * 8));
#pragma unroll
        for (int j = 0; j < 8; j++) {
            if ((comp[j] & hi_mask) == prefix_cur)
                atomicAdd(&hist[(unsigned)(comp[j] >> (p * 8)) & 255u], 1u);
        }
        __syncthreads();
        for (int off = 1; off < 256; off <<= 1) {
            unsigned vv = 0;
            if (tid < 256 && tid + off < 256) vv = hist[tid + off];
            __syncthreads();
            if (tid < 256) hist[tid] += vv;
            __syncthreads();
        }
        int tgt = s_target;
        __syncthreads();
        if (tid < 256) {
            unsigned sv = hist[tid];
            unsigned sn = (tid < 255) ? hist[tid + 1] : 0u;
            if ((int)sv >= tgt && (int)sn < tgt) {
                s_prefix = prefix_cur | ((unsigned long long)tid << (p * 8));
                s_target = tgt - (int)sn;
            }
        }
        __syncthreads();
    }
    const unsigned long long T = s_prefix;   // exact MAXC-th largest approx

    // ---- collect the MAXC candidates ---------------------------------------
#pragma unroll
    for (int j = 0; j < 8; j++) {
        if (comp[j] >= T) {
            int pos = atomicAdd(&s_cnt, 1);
            if (pos < SORTN) s_top[pos] = comp[j];
        }
    }
    __syncthreads();

    // ---- exact rescore: 4-thread groups, one candidate each ----------------
    {
        const int c = tid >> 2;          // 0..127
        const int l4 = tid & 3;
        if (c < MAXC) {
            int oc = OUTF - 1 - (int)(s_top[c] & 0xFFFFFFFFu);
            const float* wrow = W + (size_t)oc * INF;
            float part = 0.f;
#pragma unroll 4
            for (int k = l4; k < KF; k += 4)
                part += sx[k] * __ldg(&wrow[sc[k]]);
            part += __shfl_down_sync(0xFFFFFFFFu, part, 2);
            part += __shfl_down_sync(0xFFFFFFFFu, part, 1);
            if (l4 == 0) {
                float ex = part + bias[oc];
                s_top[c] = ((unsigned long long)f2key(ex) << 32) |
                           (unsigned)(OUTF - 1 - oc);
            }
        } else if (l4 == 0) {
            s_top[c] = 0ULL;             // pad: smallest possible composite
        }
    }
    __syncthreads();

    // ---- bitonic sort descending (SORTN=128 elements) -----------------------
    for (int k2 = 2; k2 <= SORTN; k2 <<= 1) {
        for (int j = k2 >> 1; j > 0; j >>= 1) {
            if (tid < SORTN) {
                int ixj = tid ^ j;
                if (ixj > tid) {
                    bool desc = ((tid & k2) == 0);
                    unsigned long long aa = s_top[tid], bb2 = s_top[ixj];
                    if (desc ? (aa < bb2) : (aa > bb2)) {
                        s_top[tid] = bb2; s_top[ixj] = aa;
                    }
                }
            }
            __syncthreads();
        }
    }

    // ---- write: [B*64 vals][B*64 indices-as-float] -------------------------
    if (tid < TOPK) {
        unsigned long long c = s_top[tid];
        out[b * TOPK + tid] = key2f((unsigned)(c >> 32));
        if (write_idx)
            out[BB * TOPK + b * TOPK + tid] =
                (float)(OUTF - 1 - (int)(c & 0xFFFFFFFFu));
    }
}

// ---------------------------------------------------------------------------
extern "C" void kernel_launch(void* const* d_in, const int* in_sizes, int n_in,
                              void* d_out, int out_size) {
    const float* x    = (const float*)d_in[0];
    const float* w    = (const float*)d_in[1];
    const float* bias = (const float*)d_in[2];
    const int*   pidx = (const int*)d_in[3];
    (void)n_in;

    dim3 tg(INF / 64, OUTF / 64);
    transpose_kernel<<<tg, 256>>>(w);

    int write_idx = (out_size >= 2 * BB * TOPK) ? 1 : 0;
    router_kernel<<<BB, 512>>>(x, w, bias, pidx, (float*)d_out, write_idx);
}